// round 11
// baseline (speedup 1.0000x reference)
#include <cuda_runtime.h>
#include <cuda_fp16.h>
#include <math.h>
#include <stdint.h>

#define BB 2
#define TT 2048
#define DD 1024
#define RR (BB*TT)   // 4096 rows

// -------- scratch (device globals; no runtime allocation) --------
__device__ __half g_h1[RR*DD];
__device__ __half g_q [RR*DD];
__device__ __half g_k [RR*256];
__device__ __half g_v [RR*256];
__device__ __half g_ao[RR*DD];
__device__ float  g_x1[RR*DD];
__device__ __half g_h2[RR*DD];
__device__ __half g_f1[RR*4*DD];
// fp16 weights [K, N]
__device__ __half g_wq[DD*DD];
__device__ __half g_wk[DD*256];
__device__ __half g_wv[DD*256];
__device__ __half g_wo[DD*DD];
__device__ __half g_w1[DD*4*DD];
__device__ __half g_w2[4*DD*DD];

__device__ __forceinline__ uint32_t smaddr(const void* p) {
    return (uint32_t)__cvta_generic_to_shared(p);
}
__device__ __forceinline__ void cp16(uint32_t dst, const void* src) {
    asm volatile("cp.async.cg.shared.global [%0], [%1], 16;" :: "r"(dst), "l"(src));
}
#define CP_COMMIT() asm volatile("cp.async.commit_group;" ::: "memory")
#define CP_WAIT(n)  asm volatile("cp.async.wait_group %0;" :: "n"(n) : "memory")

__device__ __forceinline__ void ldsm_x4(uint32_t& r0, uint32_t& r1, uint32_t& r2, uint32_t& r3, uint32_t a) {
    asm volatile("ldmatrix.sync.aligned.m8n8.x4.shared.b16 {%0,%1,%2,%3}, [%4];"
                 : "=r"(r0), "=r"(r1), "=r"(r2), "=r"(r3) : "r"(a));
}
__device__ __forceinline__ void ldsm_x4t(uint32_t& r0, uint32_t& r1, uint32_t& r2, uint32_t& r3, uint32_t a) {
    asm volatile("ldmatrix.sync.aligned.m8n8.x4.trans.shared.b16 {%0,%1,%2,%3}, [%4];"
                 : "=r"(r0), "=r"(r1), "=r"(r2), "=r"(r3) : "r"(a));
}
__device__ __forceinline__ void ldsm_x2(uint32_t& r0, uint32_t& r1, uint32_t a) {
    asm volatile("ldmatrix.sync.aligned.m8n8.x2.shared.b16 {%0,%1}, [%2];"
                 : "=r"(r0), "=r"(r1) : "r"(a));
}
__device__ __forceinline__ void ldsm_x2t(uint32_t& r0, uint32_t& r1, uint32_t a) {
    asm volatile("ldmatrix.sync.aligned.m8n8.x2.trans.shared.b16 {%0,%1}, [%2];"
                 : "=r"(r0), "=r"(r1) : "r"(a));
}
#define MMA16(c, a0,a1,a2,a3, b0,b1) \
    asm volatile("mma.sync.aligned.m16n8k16.row.col.f32.f16.f16.f32 " \
                 "{%0,%1,%2,%3}, {%4,%5,%6,%7}, {%8,%9}, {%0,%1,%2,%3};" \
                 : "+f"((c)[0]), "+f"((c)[1]), "+f"((c)[2]), "+f"((c)[3]) \
                 : "r"(a0), "r"(a1), "r"(a2), "r"(a3), "r"(b0), "r"(b1))

__device__ __forceinline__ uint32_t h2pack(float x, float y) {
    __half2 h = __floats2half2_rn(x, y);
    return *reinterpret_cast<uint32_t*>(&h);
}
__device__ __forceinline__ float ex2f(float x) {
    float y;
    asm("ex2.approx.ftz.f32 %0, %1;" : "=f"(y) : "f"(x));
    return y;
}

// ===================== weight conversion (fp32 -> fp16) =====================
#define C0 262144
#define C1 327680
#define C2 393216
#define C3 655360
#define C4 1703936
#define C5 2752512
__global__ void cvt_w(const float* __restrict__ s0, const float* __restrict__ s1,
                      const float* __restrict__ s2, const float* __restrict__ s3,
                      const float* __restrict__ s4, const float* __restrict__ s5,
                      __half* d0, __half* d1, __half* d2,
                      __half* d3, __half* d4, __half* d5) {
    const int i = blockIdx.x * blockDim.x + threadIdx.x;
    if (i >= C5) return;
    const float* s; __half* d; int base;
    if      (i < C0) { s = s0; d = d0; base = 0;  }
    else if (i < C1) { s = s1; d = d1; base = C0; }
    else if (i < C2) { s = s2; d = d2; base = C1; }
    else if (i < C3) { s = s3; d = d3; base = C2; }
    else if (i < C4) { s = s4; d = d4; base = C3; }
    else             { s = s5; d = d5; base = C4; }
    const int j = i - base;
    float4 v = reinterpret_cast<const float4*>(s)[j];
    uint2 u = { h2pack(v.x, v.y), h2pack(v.z, v.w) };
    reinterpret_cast<uint2*>(d)[j] = u;
}

// ===================== LayerNorm (fp32 in, fp16 out) =====================
__device__ __forceinline__ float block_sum256(float v, float* sh) {
    #pragma unroll
    for (int o = 16; o; o >>= 1) v += __shfl_xor_sync(0xffffffffu, v, o);
    if ((threadIdx.x & 31) == 0) sh[threadIdx.x >> 5] = v;
    __syncthreads();
    float t = sh[threadIdx.x & 7];
    #pragma unroll
    for (int o = 4; o; o >>= 1) t += __shfl_xor_sync(0xffffffffu, t, o);
    __syncthreads();
    return t;
}

__global__ void ln_kernel(const float* __restrict__ x, const float* __restrict__ gw,
                          const float* __restrict__ bw, __half* __restrict__ out) {
    __shared__ float sh[8];
    const int row = blockIdx.x;
    const float4* xr = reinterpret_cast<const float4*>(x + (size_t)row * DD);
    float4 v = xr[threadIdx.x];
    float s = v.x + v.y + v.z + v.w;
    float tot = block_sum256(s, sh);
    float mean = tot * (1.0f / DD);
    float dx = v.x - mean, dy = v.y - mean, dz = v.z - mean, dw = v.w - mean;
    float s2 = dx*dx + dy*dy + dz*dz + dw*dw;
    float tot2 = block_sum256(s2, sh);
    float rstd = rsqrtf(tot2 * (1.0f / DD) + 1e-5f);
    float4 g4 = reinterpret_cast<const float4*>(gw)[threadIdx.x];
    float4 b4 = reinterpret_cast<const float4*>(bw)[threadIdx.x];
    uint2 o = { h2pack(g4.x * dx * rstd + b4.x, g4.y * dy * rstd + b4.y),
                h2pack(g4.z * dz * rstd + b4.z, g4.w * dw * rstd + b4.w) };
    reinterpret_cast<uint2*>(out + (size_t)row * DD)[threadIdx.x] = o;
}

// ===================== FP16 GEMM: 128x128 tile, 4 warps (2x2), warp 64x64, 3-stage =====================
#define AST 72    // halves per A smem row (64 + 8 pad)
#define BST 136   // halves per B smem row (128 + 8 pad)
#define A_BUF (128 * AST)
#define B_BUF (64 * BST)
#define GEMM_SMEM (3 * (A_BUF + B_BUF) * (int)sizeof(__half))

template<int EPI, bool OUTH>
__device__ __forceinline__ void gemm_body_h(
    const __half* __restrict__ A, const __half* __restrict__ Bm,
    const float* __restrict__ bias, const float* __restrict__ res,
    void* __restrict__ C, int N, int K, int brow, int bcol, float oscale) {

    extern __shared__ __half smg[];
    __half* Ab = smg;
    __half* Bb = smg + 3 * A_BUF;

    const int tid  = threadIdx.x;
    const int lane = tid & 31, wid = tid >> 5;
    const int wm = wid & 1, wn = wid >> 1;          // 2x2 warp grid
    const int g  = lane >> 2, tg = lane & 3;
    const int l15 = lane & 15;

    __half* Asv[3] = { Ab, Ab + A_BUF, Ab + 2 * A_BUF };
    __half* Bsv[3] = { Bb, Bb + B_BUF, Bb + 2 * B_BUF };

    float acc[4][8][4];
    #pragma unroll
    for (int mt = 0; mt < 4; mt++)
        #pragma unroll
        for (int nt = 0; nt < 8; nt++)
            #pragma unroll
            for (int c = 0; c < 4; c++) acc[mt][nt][c] = 0.0f;

    // copy coords (128 threads): A 128x64h = 1024 chunks, 8/thr; B 64x128h = 1024 chunks, 8/thr
    const int arow = tid >> 3, acol = (tid & 7) << 3;
    const int brw  = tid >> 4, bcl  = (tid & 15) << 3;

    const int nk = K >> 6;
    #pragma unroll
    for (int s = 0; s < 2; s++) {
        const int k0 = s << 6;
        #pragma unroll
        for (int r = 0; r < 8; r++) {
            cp16(smaddr(&Asv[s][(arow + r * 16) * AST + acol]),
                 A + (size_t)(brow + arow + r * 16) * K + k0 + acol);
            cp16(smaddr(&Bsv[s][(brw + r * 8) * BST + bcl]),
                 Bm + (size_t)(k0 + brw + r * 8) * N + bcol + bcl);
        }
        CP_COMMIT();
    }
    CP_WAIT(1);
    __syncthreads();

    int cur = 0;
    for (int kt = 0; kt < nk; kt++) {
        __half* Asc = Asv[cur];
        __half* Bsc = Bsv[cur];
        const int nxt2 = (cur + 2 >= 3) ? cur - 1 : cur + 2;
        if (kt + 2 < nk) {
            const int k0 = (kt + 2) << 6;
            #pragma unroll
            for (int r = 0; r < 8; r++) {
                cp16(smaddr(&Asv[nxt2][(arow + r * 16) * AST + acol]),
                     A + (size_t)(brow + arow + r * 16) * K + k0 + acol);
                cp16(smaddr(&Bsv[nxt2][(brw + r * 8) * BST + bcl]),
                     Bm + (size_t)(k0 + brw + r * 8) * N + bcol + bcl);
            }
            CP_COMMIT();
        }
        #pragma unroll
        for (int ks = 0; ks < 4; ks++) {
            uint32_t af[4][4], bf[8][2];
            const int koff = ks * 16 + ((lane >> 4) << 3);
            #pragma unroll
            for (int mt = 0; mt < 4; mt++)
                ldsm_x4(af[mt][0], af[mt][1], af[mt][2], af[mt][3],
                        smaddr(&Asc[(wm * 64 + mt * 16 + l15) * AST + koff]));
            #pragma unroll
            for (int np = 0; np < 4; np++)
                ldsm_x4t(bf[2*np][0], bf[2*np][1], bf[2*np+1][0], bf[2*np+1][1],
                         smaddr(&Bsc[(ks * 16 + l15) * BST + wn * 64 + np * 16 + ((lane >> 4) << 3)]));
            #pragma unroll
            for (int mt = 0; mt < 4; mt++)
                #pragma unroll
                for (int nt = 0; nt < 8; nt++)
                    MMA16(acc[mt][nt], af[mt][0], af[mt][1], af[mt][2], af[mt][3],
                          bf[nt][0], bf[nt][1]);
        }
        if (kt + 1 < nk) {
            if (kt + 2 < nk) { CP_WAIT(1); } else { CP_WAIT(0); }
        }
        __syncthreads();
        cur = (cur + 1 >= 3) ? 0 : cur + 1;
    }

    #pragma unroll
    for (int mt = 0; mt < 4; mt++) {
        #pragma unroll
        for (int half = 0; half < 2; half++) {
            const int row = brow + wm * 64 + mt * 16 + g + half * 8;
            #pragma unroll
            for (int nt = 0; nt < 8; nt++) {
                const int col = bcol + wn * 64 + nt * 8 + tg * 2;
                float v0 = acc[mt][nt][half * 2 + 0] + bias[col];
                float v1 = acc[mt][nt][half * 2 + 1] + bias[col + 1];
                if (EPI == 1) {
                    v0 = 0.5f * v0 * (1.0f + erff(v0 * 0.70710678118654752f));
                    v1 = 0.5f * v1 * (1.0f + erff(v1 * 0.70710678118654752f));
                }
                if (EPI == 2) {
                    float2 rr = *reinterpret_cast<const float2*>(res + (size_t)row * N + col);
                    v0 += rr.x; v1 += rr.y;
                }
                v0 *= oscale; v1 *= oscale;
                if (OUTH) {
                    *reinterpret_cast<uint32_t*>((__half*)C + (size_t)row * N + col) = h2pack(v0, v1);
                } else {
                    float2 o2; o2.x = v0; o2.y = v1;
                    *reinterpret_cast<float2*>((float*)C + (size_t)row * N + col) = o2;
                }
            }
        }
    }
}

template<int EPI, bool OUTH>
__global__ void __launch_bounds__(128, 2)
gemm_h(const __half* __restrict__ A, const __half* __restrict__ Bm,
       const float* __restrict__ bias, const float* __restrict__ res,
       void* __restrict__ C, int N, int K) {
    gemm_body_h<EPI, OUTH>(A, Bm, bias, res, C, N, K,
                           blockIdx.y * 128, blockIdx.x * 128, 1.0f);
}

// fused QKV: grid.x = 12 (8 q tiles, 2 k tiles, 2 v tiles)
#define QSCALE (0.125f * 1.4426950408889634f)
__global__ void __launch_bounds__(128, 2)
gemm_qkv(const __half* __restrict__ A,
         const __half* __restrict__ wq, const float* __restrict__ bq,
         const __half* __restrict__ wk, const float* __restrict__ bk,
         const __half* __restrict__ wv, const float* __restrict__ bv,
         __half* __restrict__ q, __half* __restrict__ k, __half* __restrict__ v) {
    const int bx = blockIdx.x;
    const __half* Bm; const float* bias; __half* C; int N, bcol; float sc;
    if (bx < 8)       { Bm = wq; bias = bq; C = q; N = 1024; bcol = bx * 128;        sc = QSCALE; }
    else if (bx < 10) { Bm = wk; bias = bk; C = k; N = 256;  bcol = (bx - 8) * 128;  sc = 1.0f; }
    else              { Bm = wv; bias = bv; C = v; N = 256;  bcol = (bx - 10) * 128; sc = 1.0f; }
    gemm_body_h<0, true>(A, Bm, bias, nullptr, C, N, DD, blockIdx.y * 128, bcol, sc);
}

// ===================== Flash attention (R10 proven): 4 warps x 32 q rows =====================
#define QST 72
#define KST 72
#define VST 72
#define ATTN_HALVES (128*QST + 2*64*KST + 2*64*VST)

__global__ void __launch_bounds__(128, 2)
attn_h(const __half* __restrict__ Q, const __half* __restrict__ K,
       const __half* __restrict__ V, __half* __restrict__ O) {
    extern __shared__ __half smh[];
    __half* Qs = smh;
    __half* Ks = smh + 128 * QST;
    __half* Vs = Ks + 2 * 64 * KST;

    const int tid = threadIdx.x;
    const int lane = tid & 31, w = tid >> 5;
    const int g = lane >> 2, tg = lane & 3;
    const int l15 = lane & 15;
    const int h = blockIdx.y, b = blockIdx.z, grp = h >> 2;
    const int bx = (int)gridDim.x - 1 - (int)blockIdx.x;
    const int q0 = bx << 7;

    {
        const size_t qbase = (size_t)(b * TT + q0) * DD + h * 64;
        #pragma unroll
        for (int i = 0; i < 8; i++) {
            const int f = tid + (i << 7);
            const int r = f >> 3, c = (f & 7) << 3;
            cp16(smaddr(&Qs[r * QST + c]), Q + qbase + (size_t)r * DD + c);
        }
    }
    {
        const size_t kvbase = (size_t)(b * TT) * 256 + grp * 64;
        #pragma unroll
        for (int i = 0; i < 4; i++) {
            const int f = tid + (i << 7);
            const int r = f >> 3, c = (f & 7) << 3;
            cp16(smaddr(&Ks[r * KST + c]), K + kvbase + (size_t)r * 256 + c);
            cp16(smaddr(&Vs[r * VST + c]), V + kvbase + (size_t)r * 256 + c);
        }
    }
    CP_COMMIT();
    CP_WAIT(0);
    __syncthreads();

    uint32_t qf[2][4][4];
    {
        const int koff = (lane >> 4) << 3;
        #pragma unroll
        for (int mt = 0; mt < 2; mt++)
            #pragma unroll
            for (int ks = 0; ks < 4; ks++)
                ldsm_x4(qf[mt][ks][0], qf[mt][ks][1], qf[mt][ks][2], qf[mt][ks][3],
                        smaddr(&Qs[(w * 32 + mt * 16 + l15) * QST + ks * 16 + koff]));
    }

    float oacc[2][8][4];
    #pragma unroll
    for (int mt = 0; mt < 2; mt++)
        #pragma unroll
        for (int nt = 0; nt < 8; nt++)
            #pragma unroll
            for (int c = 0; c < 4; c++) oacc[mt][nt][c] = 0.0f;
    float mrow[2][2] = {{-1e30f, -1e30f}, {-1e30f, -1e30f}};
    float lrow[2][2] = {{0.0f, 0.0f}, {0.0f, 0.0f}};

    const int roww = q0 + w * 32;

    const int jmax = 2 * bx + 1;
    for (int jt = 0; jt <= jmax; jt++) {
        const int cur = jt & 1;
        __half* Ksc = Ks + cur * (64 * KST);
        __half* Vsc = Vs + cur * (64 * VST);
        if (jt + 1 <= jmax) {
            __half* Ksn = Ks + (cur ^ 1) * (64 * KST);
            __half* Vsn = Vs + (cur ^ 1) * (64 * VST);
            const size_t kvbase = (size_t)(b * TT + ((jt + 1) << 6)) * 256 + grp * 64;
            #pragma unroll
            for (int i = 0; i < 4; i++) {
                const int f = tid + (i << 7);
                const int r = f >> 3, c = (f & 7) << 3;
                cp16(smaddr(&Ksn[r * KST + c]), K + kvbase + (size_t)r * 256 + c);
                cp16(smaddr(&Vsn[r * VST + c]), V + kvbase + (size_t)r * 256 + c);
            }
            CP_COMMIT();
        }

        const int ktile0 = jt << 6;
        if (ktile0 <= roww + 31) {
            float sacc[2][8][4];
            #pragma unroll
            for (int mt = 0; mt < 2; mt++)
                #pragma unroll
                for (int nt = 0; nt < 8; nt++)
                    #pragma unroll
                    for (int c = 0; c < 4; c++) sacc[mt][nt][c] = 0.0f;
            #pragma unroll
            for (int ks = 0; ks < 4; ks++) {
                const int koff = ks * 16 + ((l15 >> 3) << 3);
                #pragma unroll
                for (int nt = 0; nt < 8; nt++) {
                    uint32_t b0, b1;
                    ldsm_x2(b0, b1, smaddr(&Ksc[(nt * 8 + (l15 & 7)) * KST + koff]));
                    MMA16(sacc[0][nt], qf[0][ks][0], qf[0][ks][1], qf[0][ks][2], qf[0][ks][3], b0, b1);
                    MMA16(sacc[1][nt], qf[1][ks][0], qf[1][ks][1], qf[1][ks][2], qf[1][ks][3], b0, b1);
                }
            }

            if (ktile0 + 63 > roww) {
                #pragma unroll
                for (int mt = 0; mt < 2; mt++) {
                    const int r0 = roww + mt * 16 + g, r1 = r0 + 8;
                    #pragma unroll
                    for (int nt = 0; nt < 8; nt++) {
                        const int c0 = ktile0 + nt * 8 + 2 * tg;
                        if (c0 > r0)     sacc[mt][nt][0] = -1e30f;
                        if (c0 + 1 > r0) sacc[mt][nt][1] = -1e30f;
                        if (c0 > r1)     sacc[mt][nt][2] = -1e30f;
                        if (c0 + 1 > r1) sacc[mt][nt][3] = -1e30f;
                    }
                }
            }

            #pragma unroll
            for (int mt = 0; mt < 2; mt++) {
                float tm0 = -1e30f, tm1 = -1e30f;
                #pragma unroll
                for (int nt = 0; nt < 8; nt++) {
                    tm0 = fmaxf(tm0, fmaxf(sacc[mt][nt][0], sacc[mt][nt][1]));
                    tm1 = fmaxf(tm1, fmaxf(sacc[mt][nt][2], sacc[mt][nt][3]));
                }
                #pragma unroll
                for (int off = 1; off <= 2; off <<= 1) {
                    tm0 = fmaxf(tm0, __shfl_xor_sync(0xffffffffu, tm0, off));
                    tm1 = fmaxf(tm1, __shfl_xor_sync(0xffffffffu, tm1, off));
                }
                const float nm0 = fmaxf(mrow[mt][0], tm0), nm1 = fmaxf(mrow[mt][1], tm1);
                const float al0 = ex2f(mrow[mt][0] - nm0), al1 = ex2f(mrow[mt][1] - nm1);
                mrow[mt][0] = nm0; mrow[mt][1] = nm1;
                float ts0 = 0.0f, ts1 = 0.0f;
                #pragma unroll
                for (int nt = 0; nt < 8; nt++) {
                    sacc[mt][nt][0] = ex2f(sacc[mt][nt][0] - nm0);
                    sacc[mt][nt][1] = ex2f(sacc[mt][nt][1] - nm0);
                    sacc[mt][nt][2] = ex2f(sacc[mt][nt][2] - nm1);
                    sacc[mt][nt][3] = ex2f(sacc[mt][nt][3] - nm1);
                    ts0 += sacc[mt][nt][0] + sacc[mt][nt][1];
                    ts1 += sacc[mt][nt][2] + sacc[mt][nt][3];
                }
                #pragma unroll
                for (int off = 1; off <= 2; off <<= 1) {
                    ts0 += __shfl_xor_sync(0xffffffffu, ts0, off);
                    ts1 += __shfl_xor_sync(0xffffffffu, ts1, off);
                }
                lrow[mt][0] = lrow[mt][0] * al0 + ts0;
                lrow[mt][1] = lrow[mt][1] * al1 + ts1;
                #pragma unroll
                for (int nt = 0; nt < 8; nt++) {
                    oacc[mt][nt][0] *= al0; oacc[mt][nt][1] *= al0;
                    oacc[mt][nt][2] *= al1; oacc[mt][nt][3] *= al1;
                }
            }

            #pragma unroll
            for (int ks = 0; ks < 4; ks++) {
                uint32_t pa[2][4];
                #pragma unroll
                for (int mt = 0; mt < 2; mt++) {
                    pa[mt][0] = h2pack(sacc[mt][2*ks][0],   sacc[mt][2*ks][1]);
                    pa[mt][1] = h2pack(sacc[mt][2*ks][2],   sacc[mt][2*ks][3]);
                    pa[mt][2] = h2pack(sacc[mt][2*ks+1][0], sacc[mt][2*ks+1][1]);
                    pa[mt][3] = h2pack(sacc[mt][2*ks+1][2], sacc[mt][2*ks+1][3]);
                }
                #pragma unroll
                for (int nt = 0; nt < 8; nt++) {
                    uint32_t b0, b1;
                    ldsm_x2t(b0, b1, smaddr(&Vsc[(ks * 16 + l15) * VST + nt * 8]));
                    MMA16(oacc[0][nt], pa[0][0], pa[0][1], pa[0][2], pa[0][3], b0, b1);
                    MMA16(oacc[1][nt], pa[1][0], pa[1][1], pa[1][2], pa[1][3], b0, b1);
                }
            }
        }
        if (jt + 1 <= jmax) CP_WAIT(0);
        __syncthreads();
    }

    #pragma unroll
    for (int mt = 0; mt < 2; mt++) {
        const float inv0 = 1.0f / lrow[mt][0], inv1 = 1.0f / lrow[mt][1];
        const int r0 = roww + mt * 16 + g;
        const size_t ob0 = (size_t)(b * TT + r0) * DD + h * 64;
        const size_t ob1 = (size_t)(b * TT + r0 + 8) * DD + h * 64;
        #pragma unroll
        for (int nt = 0; nt < 8; nt++) {
            const int col = nt * 8 + 2 * tg;
            *reinterpret_cast<uint32_t*>(O + ob0 + col) =
                h2pack(oacc[mt][nt][0] * inv0, oacc[mt][nt][1] * inv0);
            *reinterpret_cast<uint32_t*>(O + ob1 + col) =
                h2pack(oacc[mt][nt][2] * inv1, oacc[mt][nt][3] * inv1);
        }
    }
}

// ===================== launch =====================
extern "C" void kernel_launch(void* const* d_in, const int* in_sizes, int n_in,
                              void* d_out, int out_size) {
    (void)in_sizes; (void)n_in; (void)out_size;
    const float* x   = (const float*)d_in[0];
    const float* g1  = (const float*)d_in[1];
    const float* bt1 = (const float*)d_in[2];
    const float* wq  = (const float*)d_in[3];
    const float* bq  = (const float*)d_in[4];
    const float* wk  = (const float*)d_in[5];
    const float* bk  = (const float*)d_in[6];
    const float* wv  = (const float*)d_in[7];
    const float* bv  = (const float*)d_in[8];
    const float* wo  = (const float*)d_in[9];
    const float* bo  = (const float*)d_in[10];
    const float* g2  = (const float*)d_in[11];
    const float* bt2 = (const float*)d_in[12];
    const float* w1  = (const float*)d_in[13];
    const float* b1  = (const float*)d_in[14];
    const float* w2  = (const float*)d_in[15];
    const float* b2  = (const float*)d_in[16];
    float* out = (float*)d_out;

    __half *h1, *q, *k, *v, *ao, *h2, *f1;
    float* x1;
    __half *hwq, *hwk, *hwv, *hwo, *hw1, *hw2;
    cudaGetSymbolAddress((void**)&h1, g_h1);
    cudaGetSymbolAddress((void**)&q,  g_q);
    cudaGetSymbolAddress((void**)&k,  g_k);
    cudaGetSymbolAddress((void**)&v,  g_v);
    cudaGetSymbolAddress((void**)&ao, g_ao);
    cudaGetSymbolAddress((void**)&x1, g_x1);
    cudaGetSymbolAddress((void**)&h2, g_h2);
    cudaGetSymbolAddress((void**)&f1, g_f1);
    cudaGetSymbolAddress((void**)&hwq, g_wq);
    cudaGetSymbolAddress((void**)&hwk, g_wk);
    cudaGetSymbolAddress((void**)&hwv, g_wv);
    cudaGetSymbolAddress((void**)&hwo, g_wo);
    cudaGetSymbolAddress((void**)&hw1, g_w1);
    cudaGetSymbolAddress((void**)&hw2, g_w2);

    const int ATTN_SMEM = ATTN_HALVES * (int)sizeof(__half);
    cudaFuncSetAttribute(attn_h, cudaFuncAttributeMaxDynamicSharedMemorySize, ATTN_SMEM);
    cudaFuncSetAttribute(gemm_h<1, true>,  cudaFuncAttributeMaxDynamicSharedMemorySize, GEMM_SMEM);
    cudaFuncSetAttribute(gemm_h<2, false>, cudaFuncAttributeMaxDynamicSharedMemorySize, GEMM_SMEM);
    cudaFuncSetAttribute(gemm_qkv,         cudaFuncAttributeMaxDynamicSharedMemorySize, GEMM_SMEM);

    // 0. weights fp32 -> fp16
    cvt_w<<<(C5 + 255) / 256, 256>>>(wq, wk, wv, wo, w1, w2, hwq, hwk, hwv, hwo, hw1, hw2);
    // 1. h1 = LN(x)
    ln_kernel<<<RR, 256>>>(x, g1, bt1, h1);
    // 2. fused q/k/v (q pre-scaled by 0.125*log2e)
    gemm_qkv<<<dim3(12, RR / 128), 128, GEMM_SMEM>>>(h1, hwq, bq, hwk, bk, hwv, bv, q, k, v);
    // 3. attention
    attn_h<<<dim3(TT / 128, 16, BB), 128, ATTN_SMEM>>>(q, k, v, ao);
    // 4. x1 = x + ao @ wo + bo   (fp32 out)
    gemm_h<2, false><<<dim3(DD / 128, RR / 128), 128, GEMM_SMEM>>>(ao, hwo, bo, x, x1, DD, DD);
    // 5. h2 = LN(x1)
    ln_kernel<<<RR, 256>>>(x1, g2, bt2, h2);
    // 6. f1 = gelu(h2 @ w1 + b1)  (fp16 out)
    gemm_h<1, true><<<dim3(4 * DD / 128, RR / 128), 128, GEMM_SMEM>>>(h2, hw1, b1, nullptr, f1, 4 * DD, DD);
    // 7. out = x1 + f1 @ w2 + b2  (fp32 out)
    gemm_h<2, false><<<dim3(DD / 128, RR / 128), 128, GEMM_SMEM>>>(f1, hw2, b2, x1, out, DD, 4 * DD);
}

// round 12
// speedup vs baseline: 1.0336x; 1.0336x over previous
#include <cuda_runtime.h>
#include <cuda_fp16.h>
#include <math.h>
#include <stdint.h>

#define BB 2
#define TT 2048
#define DD 1024
#define RR (BB*TT)   // 4096 rows

// -------- scratch (device globals; no runtime allocation) --------
__device__ __half g_h1[RR*DD];
__device__ __half g_q [RR*DD];
__device__ __half g_k [RR*256];
__device__ __half g_v [RR*256];
__device__ __half g_ao[RR*DD];
__device__ float  g_x1[RR*DD];
__device__ __half g_h2[RR*DD];
__device__ __half g_f1[RR*4*DD];
// fp16 weights [K, N]
__device__ __half g_wq[DD*DD];
__device__ __half g_wk[DD*256];
__device__ __half g_wv[DD*256];
__device__ __half g_wo[DD*DD];
__device__ __half g_w1[DD*4*DD];
__device__ __half g_w2[4*DD*DD];

__device__ __forceinline__ uint32_t smaddr(const void* p) {
    return (uint32_t)__cvta_generic_to_shared(p);
}
__device__ __forceinline__ void cp16(uint32_t dst, const void* src) {
    asm volatile("cp.async.cg.shared.global [%0], [%1], 16;" :: "r"(dst), "l"(src));
}
#define CP_COMMIT() asm volatile("cp.async.commit_group;" ::: "memory")
#define CP_WAIT(n)  asm volatile("cp.async.wait_group %0;" :: "n"(n) : "memory")

__device__ __forceinline__ void ldsm_x4(uint32_t& r0, uint32_t& r1, uint32_t& r2, uint32_t& r3, uint32_t a) {
    asm volatile("ldmatrix.sync.aligned.m8n8.x4.shared.b16 {%0,%1,%2,%3}, [%4];"
                 : "=r"(r0), "=r"(r1), "=r"(r2), "=r"(r3) : "r"(a));
}
__device__ __forceinline__ void ldsm_x4t(uint32_t& r0, uint32_t& r1, uint32_t& r2, uint32_t& r3, uint32_t a) {
    asm volatile("ldmatrix.sync.aligned.m8n8.x4.trans.shared.b16 {%0,%1,%2,%3}, [%4];"
                 : "=r"(r0), "=r"(r1), "=r"(r2), "=r"(r3) : "r"(a));
}
#define MMA16(c, a0,a1,a2,a3, b0,b1) \
    asm volatile("mma.sync.aligned.m16n8k16.row.col.f32.f16.f16.f32 " \
                 "{%0,%1,%2,%3}, {%4,%5,%6,%7}, {%8,%9}, {%0,%1,%2,%3};" \
                 : "+f"((c)[0]), "+f"((c)[1]), "+f"((c)[2]), "+f"((c)[3]) \
                 : "r"(a0), "r"(a1), "r"(a2), "r"(a3), "r"(b0), "r"(b1))

__device__ __forceinline__ uint32_t h2pack(float x, float y) {
    __half2 h = __floats2half2_rn(x, y);
    return *reinterpret_cast<uint32_t*>(&h);
}
__device__ __forceinline__ float ex2f(float x) {
    float y;
    asm("ex2.approx.ftz.f32 %0, %1;" : "=f"(y) : "f"(x));
    return y;
}

// ===================== weight conversion (fp32 -> fp16) =====================
#define C0 262144
#define C1 327680
#define C2 393216
#define C3 655360
#define C4 1703936
#define C5 2752512
__global__ void cvt_w(const float* __restrict__ s0, const float* __restrict__ s1,
                      const float* __restrict__ s2, const float* __restrict__ s3,
                      const float* __restrict__ s4, const float* __restrict__ s5,
                      __half* d0, __half* d1, __half* d2,
                      __half* d3, __half* d4, __half* d5) {
    const int i = blockIdx.x * blockDim.x + threadIdx.x;
    if (i >= C5) return;
    const float* s; __half* d; int base;
    if      (i < C0) { s = s0; d = d0; base = 0;  }
    else if (i < C1) { s = s1; d = d1; base = C0; }
    else if (i < C2) { s = s2; d = d2; base = C1; }
    else if (i < C3) { s = s3; d = d3; base = C2; }
    else if (i < C4) { s = s4; d = d4; base = C3; }
    else             { s = s5; d = d5; base = C4; }
    const int j = i - base;
    float4 v = reinterpret_cast<const float4*>(s)[j];
    uint2 u = { h2pack(v.x, v.y), h2pack(v.z, v.w) };
    reinterpret_cast<uint2*>(d)[j] = u;
}

// ===================== LayerNorm (fp32 in, fp16 out) =====================
__device__ __forceinline__ float block_sum256(float v, float* sh) {
    #pragma unroll
    for (int o = 16; o; o >>= 1) v += __shfl_xor_sync(0xffffffffu, v, o);
    if ((threadIdx.x & 31) == 0) sh[threadIdx.x >> 5] = v;
    __syncthreads();
    float t = sh[threadIdx.x & 7];
    #pragma unroll
    for (int o = 4; o; o >>= 1) t += __shfl_xor_sync(0xffffffffu, t, o);
    __syncthreads();
    return t;
}

__global__ void ln_kernel(const float* __restrict__ x, const float* __restrict__ gw,
                          const float* __restrict__ bw, __half* __restrict__ out) {
    __shared__ float sh[8];
    const int row = blockIdx.x;
    const float4* xr = reinterpret_cast<const float4*>(x + (size_t)row * DD);
    float4 v = xr[threadIdx.x];
    float s = v.x + v.y + v.z + v.w;
    float tot = block_sum256(s, sh);
    float mean = tot * (1.0f / DD);
    float dx = v.x - mean, dy = v.y - mean, dz = v.z - mean, dw = v.w - mean;
    float s2 = dx*dx + dy*dy + dz*dz + dw*dw;
    float tot2 = block_sum256(s2, sh);
    float rstd = rsqrtf(tot2 * (1.0f / DD) + 1e-5f);
    float4 g4 = reinterpret_cast<const float4*>(gw)[threadIdx.x];
    float4 b4 = reinterpret_cast<const float4*>(bw)[threadIdx.x];
    uint2 o = { h2pack(g4.x * dx * rstd + b4.x, g4.y * dy * rstd + b4.y),
                h2pack(g4.z * dz * rstd + b4.z, g4.w * dw * rstd + b4.w) };
    reinterpret_cast<uint2*>(out + (size_t)row * DD)[threadIdx.x] = o;
}

// ===================== FP16 GEMM (R10 proven): 128x128, 8 warps, 3-stage, k-step 64 =====================
#define AST 72    // halves per A smem row (64 + 8 pad)
#define BST 136   // halves per B smem row (128 + 8 pad)
#define A_BUF (128 * AST)
#define B_BUF (64 * BST)
#define GEMM_SMEM (3 * (A_BUF + B_BUF) * (int)sizeof(__half))

template<int EPI, bool OUTH>
__device__ __forceinline__ void gemm_body_h(
    const __half* __restrict__ A, const __half* __restrict__ Bm,
    const float* __restrict__ bias, const float* __restrict__ res,
    void* __restrict__ C, int N, int K, int brow, int bcol, float oscale) {

    extern __shared__ __half smg[];
    __half* Ab = smg;
    __half* Bb = smg + 3 * A_BUF;

    const int tid  = threadIdx.x;
    const int lane = tid & 31, wid = tid >> 5;
    const int wm = wid & 1, wn = wid >> 1;
    const int g  = lane >> 2, tg = lane & 3;
    const int l15 = lane & 15;

    __half* Asv[3] = { Ab, Ab + A_BUF, Ab + 2 * A_BUF };
    __half* Bsv[3] = { Bb, Bb + B_BUF, Bb + 2 * B_BUF };

    float acc[4][4][4];
    #pragma unroll
    for (int mt = 0; mt < 4; mt++)
        #pragma unroll
        for (int nt = 0; nt < 4; nt++)
            #pragma unroll
            for (int c = 0; c < 4; c++) acc[mt][nt][c] = 0.0f;

    const int arow = tid >> 3, acol = (tid & 7) << 3;
    const int brw  = tid >> 4, bcl  = (tid & 15) << 3;

    const int nk = K >> 6;
    #pragma unroll
    for (int s = 0; s < 2; s++) {
        const int k0 = s << 6;
        #pragma unroll
        for (int r = 0; r < 4; r++) {
            cp16(smaddr(&Asv[s][(arow + r * 32) * AST + acol]),
                 A + (size_t)(brow + arow + r * 32) * K + k0 + acol);
            cp16(smaddr(&Bsv[s][(brw + r * 16) * BST + bcl]),
                 Bm + (size_t)(k0 + brw + r * 16) * N + bcol + bcl);
        }
        CP_COMMIT();
    }
    CP_WAIT(1);
    __syncthreads();

    int cur = 0;
    for (int kt = 0; kt < nk; kt++) {
        __half* Asc = Asv[cur];
        __half* Bsc = Bsv[cur];
        const int nxt2 = (cur + 2 >= 3) ? cur - 1 : cur + 2;
        if (kt + 2 < nk) {
            const int k0 = (kt + 2) << 6;
            #pragma unroll
            for (int r = 0; r < 4; r++) {
                cp16(smaddr(&Asv[nxt2][(arow + r * 32) * AST + acol]),
                     A + (size_t)(brow + arow + r * 32) * K + k0 + acol);
                cp16(smaddr(&Bsv[nxt2][(brw + r * 16) * BST + bcl]),
                     Bm + (size_t)(k0 + brw + r * 16) * N + bcol + bcl);
            }
            CP_COMMIT();
        }
        #pragma unroll
        for (int ks = 0; ks < 4; ks++) {
            uint32_t af[4][4], bf[4][2];
            const int koff = ks * 16 + ((lane >> 4) << 3);
            #pragma unroll
            for (int mt = 0; mt < 4; mt++)
                ldsm_x4(af[mt][0], af[mt][1], af[mt][2], af[mt][3],
                        smaddr(&Asc[(wm * 64 + mt * 16 + l15) * AST + koff]));
            #pragma unroll
            for (int np = 0; np < 2; np++)
                ldsm_x4t(bf[2*np][0], bf[2*np][1], bf[2*np+1][0], bf[2*np+1][1],
                         smaddr(&Bsc[(ks * 16 + l15) * BST + wn * 32 + np * 16 + ((lane >> 4) << 3)]));
            #pragma unroll
            for (int mt = 0; mt < 4; mt++)
                #pragma unroll
                for (int nt = 0; nt < 4; nt++)
                    MMA16(acc[mt][nt], af[mt][0], af[mt][1], af[mt][2], af[mt][3],
                          bf[nt][0], bf[nt][1]);
        }
        if (kt + 1 < nk) {
            if (kt + 2 < nk) { CP_WAIT(1); } else { CP_WAIT(0); }
        }
        __syncthreads();
        cur = (cur + 1 >= 3) ? 0 : cur + 1;
    }

    #pragma unroll
    for (int mt = 0; mt < 4; mt++) {
        #pragma unroll
        for (int half = 0; half < 2; half++) {
            const int row = brow + wm * 64 + mt * 16 + g + half * 8;
            #pragma unroll
            for (int nt = 0; nt < 4; nt++) {
                const int col = bcol + wn * 32 + nt * 8 + tg * 2;
                float v0 = acc[mt][nt][half * 2 + 0] + bias[col];
                float v1 = acc[mt][nt][half * 2 + 1] + bias[col + 1];
                if (EPI == 1) {
                    v0 = 0.5f * v0 * (1.0f + erff(v0 * 0.70710678118654752f));
                    v1 = 0.5f * v1 * (1.0f + erff(v1 * 0.70710678118654752f));
                }
                if (EPI == 2) {
                    float2 rr = *reinterpret_cast<const float2*>(res + (size_t)row * N + col);
                    v0 += rr.x; v1 += rr.y;
                }
                v0 *= oscale; v1 *= oscale;
                if (OUTH) {
                    *reinterpret_cast<uint32_t*>((__half*)C + (size_t)row * N + col) = h2pack(v0, v1);
                } else {
                    float2 o2; o2.x = v0; o2.y = v1;
                    *reinterpret_cast<float2*>((float*)C + (size_t)row * N + col) = o2;
                }
            }
        }
    }
}

template<int EPI, bool OUTH>
__global__ void __launch_bounds__(256, 2)
gemm_h(const __half* __restrict__ A, const __half* __restrict__ Bm,
       const float* __restrict__ bias, const float* __restrict__ res,
       void* __restrict__ C, int N, int K) {
    gemm_body_h<EPI, OUTH>(A, Bm, bias, res, C, N, K,
                           blockIdx.y * 128, blockIdx.x * 128, 1.0f);
}

// fused QKV: grid.x = 12 (8 q tiles, 2 k tiles, 2 v tiles)
#define QSCALE (0.125f * 1.4426950408889634f)
__global__ void __launch_bounds__(256, 2)
gemm_qkv(const __half* __restrict__ A,
         const __half* __restrict__ wq, const float* __restrict__ bq,
         const __half* __restrict__ wk, const float* __restrict__ bk,
         const __half* __restrict__ wv, const float* __restrict__ bv,
         __half* __restrict__ q, __half* __restrict__ k, __half* __restrict__ v) {
    const int bx = blockIdx.x;
    const __half* Bm; const float* bias; __half* C; int N, bcol; float sc;
    if (bx < 8)       { Bm = wq; bias = bq; C = q; N = 1024; bcol = bx * 128;        sc = QSCALE; }
    else if (bx < 10) { Bm = wk; bias = bk; C = k; N = 256;  bcol = (bx - 8) * 128;  sc = 1.0f; }
    else              { Bm = wv; bias = bv; C = v; N = 256;  bcol = (bx - 10) * 128; sc = 1.0f; }
    gemm_body_h<0, true>(A, Bm, bias, nullptr, C, N, DD, blockIdx.y * 128, bcol, sc);
}

// ===================== Flash attention: 4 warps x 32 q rows, x4 ldmatrix =====================
#define QST 72
#define KST 72
#define VST 72
#define ATTN_HALVES (128*QST + 2*64*KST + 2*64*VST)

__global__ void __launch_bounds__(128, 2)
attn_h(const __half* __restrict__ Q, const __half* __restrict__ K,
       const __half* __restrict__ V, __half* __restrict__ O) {
    extern __shared__ __half smh[];
    __half* Qs = smh;
    __half* Ks = smh + 128 * QST;
    __half* Vs = Ks + 2 * 64 * KST;

    const int tid = threadIdx.x;
    const int lane = tid & 31, w = tid >> 5;
    const int g = lane >> 2, tg = lane & 3;
    const int l15 = lane & 15;
    const int h = blockIdx.y, b = blockIdx.z, grp = h >> 2;
    const int bx = (int)gridDim.x - 1 - (int)blockIdx.x;
    const int q0 = bx << 7;

    {
        const size_t qbase = (size_t)(b * TT + q0) * DD + h * 64;
        #pragma unroll
        for (int i = 0; i < 8; i++) {
            const int f = tid + (i << 7);
            const int r = f >> 3, c = (f & 7) << 3;
            cp16(smaddr(&Qs[r * QST + c]), Q + qbase + (size_t)r * DD + c);
        }
    }
    {
        const size_t kvbase = (size_t)(b * TT) * 256 + grp * 64;
        #pragma unroll
        for (int i = 0; i < 4; i++) {
            const int f = tid + (i << 7);
            const int r = f >> 3, c = (f & 7) << 3;
            cp16(smaddr(&Ks[r * KST + c]), K + kvbase + (size_t)r * 256 + c);
            cp16(smaddr(&Vs[r * VST + c]), V + kvbase + (size_t)r * 256 + c);
        }
    }
    CP_COMMIT();
    CP_WAIT(0);
    __syncthreads();

    uint32_t qf[2][4][4];
    {
        const int koff = (lane >> 4) << 3;
        #pragma unroll
        for (int mt = 0; mt < 2; mt++)
            #pragma unroll
            for (int ks = 0; ks < 4; ks++)
                ldsm_x4(qf[mt][ks][0], qf[mt][ks][1], qf[mt][ks][2], qf[mt][ks][3],
                        smaddr(&Qs[(w * 32 + mt * 16 + l15) * QST + ks * 16 + koff]));
    }

    float oacc[2][8][4];
    #pragma unroll
    for (int mt = 0; mt < 2; mt++)
        #pragma unroll
        for (int nt = 0; nt < 8; nt++)
            #pragma unroll
            for (int c = 0; c < 4; c++) oacc[mt][nt][c] = 0.0f;
    float mrow[2][2] = {{-1e30f, -1e30f}, {-1e30f, -1e30f}};
    float lrow[2][2] = {{0.0f, 0.0f}, {0.0f, 0.0f}};

    const int roww = q0 + w * 32;

    const int jmax = 2 * bx + 1;
    for (int jt = 0; jt <= jmax; jt++) {
        const int cur = jt & 1;
        __half* Ksc = Ks + cur * (64 * KST);
        __half* Vsc = Vs + cur * (64 * VST);
        if (jt + 1 <= jmax) {
            __half* Ksn = Ks + (cur ^ 1) * (64 * KST);
            __half* Vsn = Vs + (cur ^ 1) * (64 * VST);
            const size_t kvbase = (size_t)(b * TT + ((jt + 1) << 6)) * 256 + grp * 64;
            #pragma unroll
            for (int i = 0; i < 4; i++) {
                const int f = tid + (i << 7);
                const int r = f >> 3, c = (f & 7) << 3;
                cp16(smaddr(&Ksn[r * KST + c]), K + kvbase + (size_t)r * 256 + c);
                cp16(smaddr(&Vsn[r * VST + c]), V + kvbase + (size_t)r * 256 + c);
            }
            CP_COMMIT();
        }

        const int ktile0 = jt << 6;
        if (ktile0 <= roww + 31) {
            // ---- S = Q K^T : x4 K loads, each frag pair feeds 2 mt x 2 nt MMAs ----
            float sacc[2][8][4];
            #pragma unroll
            for (int mt = 0; mt < 2; mt++)
                #pragma unroll
                for (int nt = 0; nt < 8; nt++)
                    #pragma unroll
                    for (int c = 0; c < 4; c++) sacc[mt][nt][c] = 0.0f;
            #pragma unroll
            for (int ks = 0; ks < 4; ks++) {
                const int kc = ks * 16 + (((lane >> 3) & 1) << 3);
                #pragma unroll
                for (int np = 0; np < 4; np++) {
                    uint32_t b0e, b1e, b0o, b1o;
                    ldsm_x4(b0e, b1e, b0o, b1o,
                            smaddr(&Ksc[(np * 16 + ((lane >> 4) << 3) + (lane & 7)) * KST + kc]));
                    MMA16(sacc[0][2*np],   qf[0][ks][0], qf[0][ks][1], qf[0][ks][2], qf[0][ks][3], b0e, b1e);
                    MMA16(sacc[0][2*np+1], qf[0][ks][0], qf[0][ks][1], qf[0][ks][2], qf[0][ks][3], b0o, b1o);
                    MMA16(sacc[1][2*np],   qf[1][ks][0], qf[1][ks][1], qf[1][ks][2], qf[1][ks][3], b0e, b1e);
                    MMA16(sacc[1][2*np+1], qf[1][ks][0], qf[1][ks][1], qf[1][ks][2], qf[1][ks][3], b0o, b1o);
                }
            }

            if (ktile0 + 63 > roww) {
                #pragma unroll
                for (int mt = 0; mt < 2; mt++) {
                    const int r0 = roww + mt * 16 + g, r1 = r0 + 8;
                    #pragma unroll
                    for (int nt = 0; nt < 8; nt++) {
                        const int c0 = ktile0 + nt * 8 + 2 * tg;
                        if (c0 > r0)     sacc[mt][nt][0] = -1e30f;
                        if (c0 + 1 > r0) sacc[mt][nt][1] = -1e30f;
                        if (c0 > r1)     sacc[mt][nt][2] = -1e30f;
                        if (c0 + 1 > r1) sacc[mt][nt][3] = -1e30f;
                    }
                }
            }

            #pragma unroll
            for (int mt = 0; mt < 2; mt++) {
                float tm0 = -1e30f, tm1 = -1e30f;
                #pragma unroll
                for (int nt = 0; nt < 8; nt++) {
                    tm0 = fmaxf(tm0, fmaxf(sacc[mt][nt][0], sacc[mt][nt][1]));
                    tm1 = fmaxf(tm1, fmaxf(sacc[mt][nt][2], sacc[mt][nt][3]));
                }
                #pragma unroll
                for (int off = 1; off <= 2; off <<= 1) {
                    tm0 = fmaxf(tm0, __shfl_xor_sync(0xffffffffu, tm0, off));
                    tm1 = fmaxf(tm1, __shfl_xor_sync(0xffffffffu, tm1, off));
                }
                const float nm0 = fmaxf(mrow[mt][0], tm0), nm1 = fmaxf(mrow[mt][1], tm1);
                const float al0 = ex2f(mrow[mt][0] - nm0), al1 = ex2f(mrow[mt][1] - nm1);
                mrow[mt][0] = nm0; mrow[mt][1] = nm1;
                float ts0 = 0.0f, ts1 = 0.0f;
                #pragma unroll
                for (int nt = 0; nt < 8; nt++) {
                    sacc[mt][nt][0] = ex2f(sacc[mt][nt][0] - nm0);
                    sacc[mt][nt][1] = ex2f(sacc[mt][nt][1] - nm0);
                    sacc[mt][nt][2] = ex2f(sacc[mt][nt][2] - nm1);
                    sacc[mt][nt][3] = ex2f(sacc[mt][nt][3] - nm1);
                    ts0 += sacc[mt][nt][0] + sacc[mt][nt][1];
                    ts1 += sacc[mt][nt][2] + sacc[mt][nt][3];
                }
                #pragma unroll
                for (int off = 1; off <= 2; off <<= 1) {
                    ts0 += __shfl_xor_sync(0xffffffffu, ts0, off);
                    ts1 += __shfl_xor_sync(0xffffffffu, ts1, off);
                }
                lrow[mt][0] = lrow[mt][0] * al0 + ts0;
                lrow[mt][1] = lrow[mt][1] * al1 + ts1;
                #pragma unroll
                for (int nt = 0; nt < 8; nt++) {
                    oacc[mt][nt][0] *= al0; oacc[mt][nt][1] *= al0;
                    oacc[mt][nt][2] *= al1; oacc[mt][nt][3] *= al1;
                }
            }

            // ---- O += P @ V : x4t V loads, each frag pair feeds 2 mt x 2 nt MMAs ----
            #pragma unroll
            for (int ks = 0; ks < 4; ks++) {
                uint32_t pa[2][4];
                #pragma unroll
                for (int mt = 0; mt < 2; mt++) {
                    pa[mt][0] = h2pack(sacc[mt][2*ks][0],   sacc[mt][2*ks][1]);
                    pa[mt][1] = h2pack(sacc[mt][2*ks][2],   sacc[mt][2*ks][3]);
                    pa[mt][2] = h2pack(sacc[mt][2*ks+1][0], sacc[mt][2*ks+1][1]);
                    pa[mt][3] = h2pack(sacc[mt][2*ks+1][2], sacc[mt][2*ks+1][3]);
                }
                #pragma unroll
                for (int np = 0; np < 4; np++) {
                    uint32_t b0e, b1e, b0o, b1o;
                    ldsm_x4t(b0e, b1e, b0o, b1o,
                             smaddr(&Vsc[(ks * 16 + l15) * VST + np * 16 + ((lane >> 4) << 3)]));
                    MMA16(oacc[0][2*np],   pa[0][0], pa[0][1], pa[0][2], pa[0][3], b0e, b1e);
                    MMA16(oacc[0][2*np+1], pa[0][0], pa[0][1], pa[0][2], pa[0][3], b0o, b1o);
                    MMA16(oacc[1][2*np],   pa[1][0], pa[1][1], pa[1][2], pa[1][3], b0e, b1e);
                    MMA16(oacc[1][2*np+1], pa[1][0], pa[1][1], pa[1][2], pa[1][3], b0o, b1o);
                }
            }
        }
        if (jt + 1 <= jmax) CP_WAIT(0);
        __syncthreads();
    }

    #pragma unroll
    for (int mt = 0; mt < 2; mt++) {
        const float inv0 = 1.0f / lrow[mt][0], inv1 = 1.0f / lrow[mt][1];
        const int r0 = roww + mt * 16 + g;
        const size_t ob0 = (size_t)(b * TT + r0) * DD + h * 64;
        const size_t ob1 = (size_t)(b * TT + r0 + 8) * DD + h * 64;
        #pragma unroll
        for (int nt = 0; nt < 8; nt++) {
            const int col = nt * 8 + 2 * tg;
            *reinterpret_cast<uint32_t*>(O + ob0 + col) =
                h2pack(oacc[mt][nt][0] * inv0, oacc[mt][nt][1] * inv0);
            *reinterpret_cast<uint32_t*>(O + ob1 + col) =
                h2pack(oacc[mt][nt][2] * inv1, oacc[mt][nt][3] * inv1);
        }
    }
}

// ===================== launch =====================
extern "C" void kernel_launch(void* const* d_in, const int* in_sizes, int n_in,
                              void* d_out, int out_size) {
    (void)in_sizes; (void)n_in; (void)out_size;
    const float* x   = (const float*)d_in[0];
    const float* g1  = (const float*)d_in[1];
    const float* bt1 = (const float*)d_in[2];
    const float* wq  = (const float*)d_in[3];
    const float* bq  = (const float*)d_in[4];
    const float* wk  = (const float*)d_in[5];
    const float* bk  = (const float*)d_in[6];
    const float* wv  = (const float*)d_in[7];
    const float* bv  = (const float*)d_in[8];
    const float* wo  = (const float*)d_in[9];
    const float* bo  = (const float*)d_in[10];
    const float* g2  = (const float*)d_in[11];
    const float* bt2 = (const float*)d_in[12];
    const float* w1  = (const float*)d_in[13];
    const float* b1  = (const float*)d_in[14];
    const float* w2  = (const float*)d_in[15];
    const float* b2  = (const float*)d_in[16];
    float* out = (float*)d_out;

    __half *h1, *q, *k, *v, *ao, *h2, *f1;
    float* x1;
    __half *hwq, *hwk, *hwv, *hwo, *hw1, *hw2;
    cudaGetSymbolAddress((void**)&h1, g_h1);
    cudaGetSymbolAddress((void**)&q,  g_q);
    cudaGetSymbolAddress((void**)&k,  g_k);
    cudaGetSymbolAddress((void**)&v,  g_v);
    cudaGetSymbolAddress((void**)&ao, g_ao);
    cudaGetSymbolAddress((void**)&x1, g_x1);
    cudaGetSymbolAddress((void**)&h2, g_h2);
    cudaGetSymbolAddress((void**)&f1, g_f1);
    cudaGetSymbolAddress((void**)&hwq, g_wq);
    cudaGetSymbolAddress((void**)&hwk, g_wk);
    cudaGetSymbolAddress((void**)&hwv, g_wv);
    cudaGetSymbolAddress((void**)&hwo, g_wo);
    cudaGetSymbolAddress((void**)&hw1, g_w1);
    cudaGetSymbolAddress((void**)&hw2, g_w2);

    const int ATTN_SMEM = ATTN_HALVES * (int)sizeof(__half);
    cudaFuncSetAttribute(attn_h, cudaFuncAttributeMaxDynamicSharedMemorySize, ATTN_SMEM);
    cudaFuncSetAttribute(gemm_h<1, true>,  cudaFuncAttributeMaxDynamicSharedMemorySize, GEMM_SMEM);
    cudaFuncSetAttribute(gemm_h<2, false>, cudaFuncAttributeMaxDynamicSharedMemorySize, GEMM_SMEM);
    cudaFuncSetAttribute(gemm_qkv,         cudaFuncAttributeMaxDynamicSharedMemorySize, GEMM_SMEM);

    // 0. weights fp32 -> fp16
    cvt_w<<<(C5 + 255) / 256, 256>>>(wq, wk, wv, wo, w1, w2, hwq, hwk, hwv, hwo, hw1, hw2);
    // 1. h1 = LN(x)
    ln_kernel<<<RR, 256>>>(x, g1, bt1, h1);
    // 2. fused q/k/v (q pre-scaled by 0.125*log2e)
    gemm_qkv<<<dim3(12, RR / 128), 256, GEMM_SMEM>>>(h1, hwq, bq, hwk, bk, hwv, bv, q, k, v);
    // 3. attention
    attn_h<<<dim3(TT / 128, 16, BB), 128, ATTN_SMEM>>>(q, k, v, ao);
    // 4. x1 = x + ao @ wo + bo   (fp32 out)
    gemm_h<2, false><<<dim3(DD / 128, RR / 128), 256, GEMM_SMEM>>>(ao, hwo, bo, x, x1, DD, DD);
    // 5. h2 = LN(x1)
    ln_kernel<<<RR, 256>>>(x1, g2, bt2, h2);
    // 6. f1 = gelu(h2 @ w1 + b1)  (fp16 out)
    gemm_h<1, true><<<dim3(4 * DD / 128, RR / 128), 256, GEMM_SMEM>>>(h2, hw1, b1, nullptr, f1, 4 * DD, DD);
    // 7. out = x1 + f1 @ w2 + b2  (fp32 out)
    gemm_h<2, false><<<dim3(DD / 128, RR / 128), 256, GEMM_SMEM>>>(f1, hw2, b2, x1, out, DD, 4 * DD);
}

// round 13
// speedup vs baseline: 1.0428x; 1.0089x over previous
#include <cuda_runtime.h>
#include <cuda_fp16.h>
#include <math.h>
#include <stdint.h>

#define BB 2
#define TT 2048
#define DD 1024
#define RR (BB*TT)   // 4096 rows

// -------- scratch (device globals; no runtime allocation) --------
__device__ __half g_h1[RR*DD];
__device__ __half g_q [RR*DD];
__device__ __half g_k [RR*256];
__device__ __half g_v [RR*256];
__device__ __half g_ao[RR*DD];
__device__ float  g_x1[RR*DD];
__device__ __half g_h2[RR*DD];
__device__ __half g_f1[RR*4*DD];
// fp16 weights [K, N]
__device__ __half g_wq[DD*DD];
__device__ __half g_wk[DD*256];
__device__ __half g_wv[DD*256];
__device__ __half g_wo[DD*DD];
__device__ __half g_w1[DD*4*DD];
__device__ __half g_w2[4*DD*DD];

__device__ __forceinline__ uint32_t smaddr(const void* p) {
    return (uint32_t)__cvta_generic_to_shared(p);
}
__device__ __forceinline__ void cp16(uint32_t dst, const void* src) {
    asm volatile("cp.async.cg.shared.global [%0], [%1], 16;" :: "r"(dst), "l"(src));
}
#define CP_COMMIT() asm volatile("cp.async.commit_group;" ::: "memory")
#define CP_WAIT(n)  asm volatile("cp.async.wait_group %0;" :: "n"(n) : "memory")

__device__ __forceinline__ void ldsm_x4(uint32_t& r0, uint32_t& r1, uint32_t& r2, uint32_t& r3, uint32_t a) {
    asm volatile("ldmatrix.sync.aligned.m8n8.x4.shared.b16 {%0,%1,%2,%3}, [%4];"
                 : "=r"(r0), "=r"(r1), "=r"(r2), "=r"(r3) : "r"(a));
}
__device__ __forceinline__ void ldsm_x4t(uint32_t& r0, uint32_t& r1, uint32_t& r2, uint32_t& r3, uint32_t a) {
    asm volatile("ldmatrix.sync.aligned.m8n8.x4.trans.shared.b16 {%0,%1,%2,%3}, [%4];"
                 : "=r"(r0), "=r"(r1), "=r"(r2), "=r"(r3) : "r"(a));
}
__device__ __forceinline__ void ldsm_x2(uint32_t& r0, uint32_t& r1, uint32_t a) {
    asm volatile("ldmatrix.sync.aligned.m8n8.x2.shared.b16 {%0,%1}, [%2];"
                 : "=r"(r0), "=r"(r1) : "r"(a));
}
__device__ __forceinline__ void ldsm_x2t(uint32_t& r0, uint32_t& r1, uint32_t a) {
    asm volatile("ldmatrix.sync.aligned.m8n8.x2.trans.shared.b16 {%0,%1}, [%2];"
                 : "=r"(r0), "=r"(r1) : "r"(a));
}
#define MMA16(c, a0,a1,a2,a3, b0,b1) \
    asm volatile("mma.sync.aligned.m16n8k16.row.col.f32.f16.f16.f32 " \
                 "{%0,%1,%2,%3}, {%4,%5,%6,%7}, {%8,%9}, {%0,%1,%2,%3};" \
                 : "+f"((c)[0]), "+f"((c)[1]), "+f"((c)[2]), "+f"((c)[3]) \
                 : "r"(a0), "r"(a1), "r"(a2), "r"(a3), "r"(b0), "r"(b1))

__device__ __forceinline__ uint32_t h2pack(float x, float y) {
    __half2 h = __floats2half2_rn(x, y);
    return *reinterpret_cast<uint32_t*>(&h);
}
__device__ __forceinline__ float ex2f(float x) {
    float y;
    asm("ex2.approx.ftz.f32 %0, %1;" : "=f"(y) : "f"(x));
    return y;
}
// pack two f32 to half2 (lo=a, hi=b) then 2^x elementwise
__device__ __forceinline__ uint32_t h2exp2(float a, float b) {
    uint32_t h, e;
    asm("cvt.rn.f16x2.f32 %0, %1, %2;" : "=r"(h) : "f"(b), "f"(a));
    asm("ex2.approx.f16x2 %0, %1;" : "=r"(e) : "r"(h));
    return e;
}

// ===================== fused weight-cvt + LN1 =====================
#define C0 262144
#define C1 327680
#define C2 393216
#define C3 655360
#define C4 1703936
#define C5 2752512
#define CVT_BLOCKS (C5/256)   // 10752

__device__ __forceinline__ float block_sum256(float v, float* sh) {
    #pragma unroll
    for (int o = 16; o; o >>= 1) v += __shfl_xor_sync(0xffffffffu, v, o);
    if ((threadIdx.x & 31) == 0) sh[threadIdx.x >> 5] = v;
    __syncthreads();
    float t = sh[threadIdx.x & 7];
    #pragma unroll
    for (int o = 4; o; o >>= 1) t += __shfl_xor_sync(0xffffffffu, t, o);
    __syncthreads();
    return t;
}

__device__ __forceinline__ void ln_body(const float* __restrict__ x,
                                        const float* __restrict__ gw,
                                        const float* __restrict__ bw,
                                        __half* __restrict__ out, int row) {
    __shared__ float sh[8];
    const float4* xr = reinterpret_cast<const float4*>(x + (size_t)row * DD);
    float4 v = xr[threadIdx.x];
    float s = v.x + v.y + v.z + v.w;
    float tot = block_sum256(s, sh);
    float mean = tot * (1.0f / DD);
    float dx = v.x - mean, dy = v.y - mean, dz = v.z - mean, dw = v.w - mean;
    float s2 = dx*dx + dy*dy + dz*dz + dw*dw;
    float tot2 = block_sum256(s2, sh);
    float rstd = rsqrtf(tot2 * (1.0f / DD) + 1e-5f);
    float4 g4 = reinterpret_cast<const float4*>(gw)[threadIdx.x];
    float4 b4 = reinterpret_cast<const float4*>(bw)[threadIdx.x];
    uint2 o = { h2pack(g4.x * dx * rstd + b4.x, g4.y * dy * rstd + b4.y),
                h2pack(g4.z * dz * rstd + b4.z, g4.w * dw * rstd + b4.w) };
    reinterpret_cast<uint2*>(out + (size_t)row * DD)[threadIdx.x] = o;
}

__global__ void cvt_ln(const float* __restrict__ s0, const float* __restrict__ s1,
                       const float* __restrict__ s2, const float* __restrict__ s3,
                       const float* __restrict__ s4, const float* __restrict__ s5,
                       __half* d0, __half* d1, __half* d2,
                       __half* d3, __half* d4, __half* d5,
                       const float* __restrict__ x, const float* __restrict__ g1,
                       const float* __restrict__ bt1, __half* __restrict__ h1) {
    if (blockIdx.x >= CVT_BLOCKS) {
        ln_body(x, g1, bt1, h1, blockIdx.x - CVT_BLOCKS);
        return;
    }
    const int i = blockIdx.x * 256 + threadIdx.x;
    const float* s; __half* d; int base;
    if      (i < C0) { s = s0; d = d0; base = 0;  }
    else if (i < C1) { s = s1; d = d1; base = C0; }
    else if (i < C2) { s = s2; d = d2; base = C1; }
    else if (i < C3) { s = s3; d = d3; base = C2; }
    else if (i < C4) { s = s4; d = d4; base = C3; }
    else             { s = s5; d = d5; base = C4; }
    const int j = i - base;
    float4 v = reinterpret_cast<const float4*>(s)[j];
    uint2 u = { h2pack(v.x, v.y), h2pack(v.z, v.w) };
    reinterpret_cast<uint2*>(d)[j] = u;
}

__global__ void ln_kernel(const float* __restrict__ x, const float* __restrict__ gw,
                          const float* __restrict__ bw, __half* __restrict__ out) {
    ln_body(x, gw, bw, out, blockIdx.x);
}

// ===================== FP16 GEMM (R10 proven): 128x128, 8 warps, 3-stage, k-step 64 =====================
#define AST 72
#define BST 136
#define A_BUF (128 * AST)
#define B_BUF (64 * BST)
#define GEMM_SMEM (3 * (A_BUF + B_BUF) * (int)sizeof(__half))

template<int EPI, bool OUTH>
__device__ __forceinline__ void gemm_body_h(
    const __half* __restrict__ A, const __half* __restrict__ Bm,
    const float* __restrict__ bias, const float* __restrict__ res,
    void* __restrict__ C, int N, int K, int brow, int bcol, float oscale) {

    extern __shared__ __half smg[];
    __half* Ab = smg;
    __half* Bb = smg + 3 * A_BUF;

    const int tid  = threadIdx.x;
    const int lane = tid & 31, wid = tid >> 5;
    const int wm = wid & 1, wn = wid >> 1;
    const int g  = lane >> 2, tg = lane & 3;
    const int l15 = lane & 15;

    __half* Asv[3] = { Ab, Ab + A_BUF, Ab + 2 * A_BUF };
    __half* Bsv[3] = { Bb, Bb + B_BUF, Bb + 2 * B_BUF };

    float acc[4][4][4];
    #pragma unroll
    for (int mt = 0; mt < 4; mt++)
        #pragma unroll
        for (int nt = 0; nt < 4; nt++)
            #pragma unroll
            for (int c = 0; c < 4; c++) acc[mt][nt][c] = 0.0f;

    const int arow = tid >> 3, acol = (tid & 7) << 3;
    const int brw  = tid >> 4, bcl  = (tid & 15) << 3;

    const int nk = K >> 6;
    #pragma unroll
    for (int s = 0; s < 2; s++) {
        const int k0 = s << 6;
        #pragma unroll
        for (int r = 0; r < 4; r++) {
            cp16(smaddr(&Asv[s][(arow + r * 32) * AST + acol]),
                 A + (size_t)(brow + arow + r * 32) * K + k0 + acol);
            cp16(smaddr(&Bsv[s][(brw + r * 16) * BST + bcl]),
                 Bm + (size_t)(k0 + brw + r * 16) * N + bcol + bcl);
        }
        CP_COMMIT();
    }
    CP_WAIT(1);
    __syncthreads();

    int cur = 0;
    for (int kt = 0; kt < nk; kt++) {
        __half* Asc = Asv[cur];
        __half* Bsc = Bsv[cur];
        const int nxt2 = (cur + 2 >= 3) ? cur - 1 : cur + 2;
        if (kt + 2 < nk) {
            const int k0 = (kt + 2) << 6;
            #pragma unroll
            for (int r = 0; r < 4; r++) {
                cp16(smaddr(&Asv[nxt2][(arow + r * 32) * AST + acol]),
                     A + (size_t)(brow + arow + r * 32) * K + k0 + acol);
                cp16(smaddr(&Bsv[nxt2][(brw + r * 16) * BST + bcl]),
                     Bm + (size_t)(k0 + brw + r * 16) * N + bcol + bcl);
            }
            CP_COMMIT();
        }
        #pragma unroll
        for (int ks = 0; ks < 4; ks++) {
            uint32_t af[4][4], bf[4][2];
            const int koff = ks * 16 + ((lane >> 4) << 3);
            #pragma unroll
            for (int mt = 0; mt < 4; mt++)
                ldsm_x4(af[mt][0], af[mt][1], af[mt][2], af[mt][3],
                        smaddr(&Asc[(wm * 64 + mt * 16 + l15) * AST + koff]));
            #pragma unroll
            for (int np = 0; np < 2; np++)
                ldsm_x4t(bf[2*np][0], bf[2*np][1], bf[2*np+1][0], bf[2*np+1][1],
                         smaddr(&Bsc[(ks * 16 + l15) * BST + wn * 32 + np * 16 + ((lane >> 4) << 3)]));
            #pragma unroll
            for (int mt = 0; mt < 4; mt++)
                #pragma unroll
                for (int nt = 0; nt < 4; nt++)
                    MMA16(acc[mt][nt], af[mt][0], af[mt][1], af[mt][2], af[mt][3],
                          bf[nt][0], bf[nt][1]);
        }
        if (kt + 1 < nk) {
            if (kt + 2 < nk) { CP_WAIT(1); } else { CP_WAIT(0); }
        }
        __syncthreads();
        cur = (cur + 1 >= 3) ? 0 : cur + 1;
    }

    #pragma unroll
    for (int mt = 0; mt < 4; mt++) {
        #pragma unroll
        for (int half = 0; half < 2; half++) {
            const int row = brow + wm * 64 + mt * 16 + g + half * 8;
            #pragma unroll
            for (int nt = 0; nt < 4; nt++) {
                const int col = bcol + wn * 32 + nt * 8 + tg * 2;
                float v0 = acc[mt][nt][half * 2 + 0] + bias[col];
                float v1 = acc[mt][nt][half * 2 + 1] + bias[col + 1];
                if (EPI == 1) {
                    v0 = 0.5f * v0 * (1.0f + erff(v0 * 0.70710678118654752f));
                    v1 = 0.5f * v1 * (1.0f + erff(v1 * 0.70710678118654752f));
                }
                if (EPI == 2) {
                    float2 rr = *reinterpret_cast<const float2*>(res + (size_t)row * N + col);
                    v0 += rr.x; v1 += rr.y;
                }
                v0 *= oscale; v1 *= oscale;
                if (OUTH) {
                    *reinterpret_cast<uint32_t*>((__half*)C + (size_t)row * N + col) = h2pack(v0, v1);
                } else {
                    float2 o2; o2.x = v0; o2.y = v1;
                    *reinterpret_cast<float2*>((float*)C + (size_t)row * N + col) = o2;
                }
            }
        }
    }
}

template<int EPI, bool OUTH>
__global__ void __launch_bounds__(256, 2)
gemm_h(const __half* __restrict__ A, const __half* __restrict__ Bm,
       const float* __restrict__ bias, const float* __restrict__ res,
       void* __restrict__ C, int N, int K) {
    gemm_body_h<EPI, OUTH>(A, Bm, bias, res, C, N, K,
                           blockIdx.y * 128, blockIdx.x * 128, 1.0f);
}

#define QSCALE (0.125f * 1.4426950408889634f)
__global__ void __launch_bounds__(256, 2)
gemm_qkv(const __half* __restrict__ A,
         const __half* __restrict__ wq, const float* __restrict__ bq,
         const __half* __restrict__ wk, const float* __restrict__ bk,
         const __half* __restrict__ wv, const float* __restrict__ bv,
         __half* __restrict__ q, __half* __restrict__ k, __half* __restrict__ v) {
    const int bx = blockIdx.x;
    const __half* Bm; const float* bias; __half* C; int N, bcol; float sc;
    if (bx < 8)       { Bm = wq; bias = bq; C = q; N = 1024; bcol = bx * 128;        sc = QSCALE; }
    else if (bx < 10) { Bm = wk; bias = bk; C = k; N = 256;  bcol = (bx - 8) * 128;  sc = 1.0f; }
    else              { Bm = wv; bias = bv; C = v; N = 256;  bcol = (bx - 10) * 128; sc = 1.0f; }
    gemm_body_h<0, true>(A, Bm, bias, nullptr, C, N, DD, blockIdx.y * 128, bcol, sc);
}

// ===================== Flash attention: 4 warps x 32 q rows, f16x2 exp, MMA row-sum =====================
#define QST 72
#define KST 72
#define VST 72
#define ATTN_HALVES (128*QST + 2*64*KST + 2*64*VST)

__global__ void __launch_bounds__(128, 2)
attn_h(const __half* __restrict__ Q, const __half* __restrict__ K,
       const __half* __restrict__ V, __half* __restrict__ O) {
    extern __shared__ __half smh[];
    __half* Qs = smh;
    __half* Ks = smh + 128 * QST;
    __half* Vs = Ks + 2 * 64 * KST;

    const int tid = threadIdx.x;
    const int lane = tid & 31, w = tid >> 5;
    const int g = lane >> 2, tg = lane & 3;
    const int l15 = lane & 15;
    const int h = blockIdx.y, b = blockIdx.z, grp = h >> 2;
    const int bx = (int)gridDim.x - 1 - (int)blockIdx.x;
    const int q0 = bx << 7;

    {
        const size_t qbase = (size_t)(b * TT + q0) * DD + h * 64;
        #pragma unroll
        for (int i = 0; i < 8; i++) {
            const int f = tid + (i << 7);
            const int r = f >> 3, c = (f & 7) << 3;
            cp16(smaddr(&Qs[r * QST + c]), Q + qbase + (size_t)r * DD + c);
        }
    }
    {
        const size_t kvbase = (size_t)(b * TT) * 256 + grp * 64;
        #pragma unroll
        for (int i = 0; i < 4; i++) {
            const int f = tid + (i << 7);
            const int r = f >> 3, c = (f & 7) << 3;
            cp16(smaddr(&Ks[r * KST + c]), K + kvbase + (size_t)r * 256 + c);
            cp16(smaddr(&Vs[r * VST + c]), V + kvbase + (size_t)r * 256 + c);
        }
    }
    // ones column for row-sum trick: V smem cols 64..71 = [1,0,0,0,0,0,0,0]
    // (cp.async only writes cols 0..63; written once for both buffers)
    {
        const int buf = tid >> 6, r = tid & 63;
        uint4 ones = { 0x3C00u, 0u, 0u, 0u };
        *reinterpret_cast<uint4*>(&Vs[buf * (64 * VST) + r * VST + 64]) = ones;
    }
    CP_COMMIT();
    CP_WAIT(0);
    __syncthreads();

    uint32_t qf[2][4][4];
    {
        const int koff = (lane >> 4) << 3;
        #pragma unroll
        for (int mt = 0; mt < 2; mt++)
            #pragma unroll
            for (int ks = 0; ks < 4; ks++)
                ldsm_x4(qf[mt][ks][0], qf[mt][ks][1], qf[mt][ks][2], qf[mt][ks][3],
                        smaddr(&Qs[(w * 32 + mt * 16 + l15) * QST + ks * 16 + koff]));
    }

    // oacc[mt][0..7] = output cols, oacc[mt][8] = row-sum (l) accumulator
    float oacc[2][9][4];
    #pragma unroll
    for (int mt = 0; mt < 2; mt++)
        #pragma unroll
        for (int nt = 0; nt < 9; nt++)
            #pragma unroll
            for (int c = 0; c < 4; c++) oacc[mt][nt][c] = 0.0f;
    float mrow[2][2] = {{-1e30f, -1e30f}, {-1e30f, -1e30f}};

    const int roww = q0 + w * 32;

    const int jmax = 2 * bx + 1;
    for (int jt = 0; jt <= jmax; jt++) {
        const int cur = jt & 1;
        __half* Ksc = Ks + cur * (64 * KST);
        __half* Vsc = Vs + cur * (64 * VST);
        if (jt + 1 <= jmax) {
            __half* Ksn = Ks + (cur ^ 1) * (64 * KST);
            __half* Vsn = Vs + (cur ^ 1) * (64 * VST);
            const size_t kvbase = (size_t)(b * TT + ((jt + 1) << 6)) * 256 + grp * 64;
            #pragma unroll
            for (int i = 0; i < 4; i++) {
                const int f = tid + (i << 7);
                const int r = f >> 3, c = (f & 7) << 3;
                cp16(smaddr(&Ksn[r * KST + c]), K + kvbase + (size_t)r * 256 + c);
                cp16(smaddr(&Vsn[r * VST + c]), V + kvbase + (size_t)r * 256 + c);
            }
            CP_COMMIT();
        }

        const int ktile0 = jt << 6;
        if (ktile0 <= roww + 31) {
            float sacc[2][8][4];
            #pragma unroll
            for (int mt = 0; mt < 2; mt++)
                #pragma unroll
                for (int nt = 0; nt < 8; nt++)
                    #pragma unroll
                    for (int c = 0; c < 4; c++) sacc[mt][nt][c] = 0.0f;
            #pragma unroll
            for (int ks = 0; ks < 4; ks++) {
                const int koff = ks * 16 + ((l15 >> 3) << 3);
                #pragma unroll
                for (int nt = 0; nt < 8; nt++) {
                    uint32_t b0, b1;
                    ldsm_x2(b0, b1, smaddr(&Ksc[(nt * 8 + (l15 & 7)) * KST + koff]));
                    MMA16(sacc[0][nt], qf[0][ks][0], qf[0][ks][1], qf[0][ks][2], qf[0][ks][3], b0, b1);
                    MMA16(sacc[1][nt], qf[1][ks][0], qf[1][ks][1], qf[1][ks][2], qf[1][ks][3], b0, b1);
                }
            }

            if (ktile0 + 63 > roww) {
                #pragma unroll
                for (int mt = 0; mt < 2; mt++) {
                    const int r0 = roww + mt * 16 + g, r1 = r0 + 8;
                    #pragma unroll
                    for (int nt = 0; nt < 8; nt++) {
                        const int c0 = ktile0 + nt * 8 + 2 * tg;
                        if (c0 > r0)     sacc[mt][nt][0] = -1e30f;
                        if (c0 + 1 > r0) sacc[mt][nt][1] = -1e30f;
                        if (c0 > r1)     sacc[mt][nt][2] = -1e30f;
                        if (c0 + 1 > r1) sacc[mt][nt][3] = -1e30f;
                    }
                }
            }

            // online softmax: max + f16x2 exp (P fragments produced directly)
            uint32_t sp[2][8][2];
            #pragma unroll
            for (int mt = 0; mt < 2; mt++) {
                float tm0 = -1e30f, tm1 = -1e30f;
                #pragma unroll
                for (int nt = 0; nt < 8; nt++) {
                    tm0 = fmaxf(tm0, fmaxf(sacc[mt][nt][0], sacc[mt][nt][1]));
                    tm1 = fmaxf(tm1, fmaxf(sacc[mt][nt][2], sacc[mt][nt][3]));
                }
                #pragma unroll
                for (int off = 1; off <= 2; off <<= 1) {
                    tm0 = fmaxf(tm0, __shfl_xor_sync(0xffffffffu, tm0, off));
                    tm1 = fmaxf(tm1, __shfl_xor_sync(0xffffffffu, tm1, off));
                }
                const float nm0 = fmaxf(mrow[mt][0], tm0), nm1 = fmaxf(mrow[mt][1], tm1);
                const float al0 = ex2f(mrow[mt][0] - nm0), al1 = ex2f(mrow[mt][1] - nm1);
                mrow[mt][0] = nm0; mrow[mt][1] = nm1;
                #pragma unroll
                for (int nt = 0; nt < 8; nt++) {
                    sp[mt][nt][0] = h2exp2(sacc[mt][nt][0] - nm0, sacc[mt][nt][1] - nm0);
                    sp[mt][nt][1] = h2exp2(sacc[mt][nt][2] - nm1, sacc[mt][nt][3] - nm1);
                }
                #pragma unroll
                for (int nt = 0; nt < 9; nt++) {
                    oacc[mt][nt][0] *= al0; oacc[mt][nt][1] *= al0;
                    oacc[mt][nt][2] *= al1; oacc[mt][nt][3] *= al1;
                }
            }

            // O += P @ V  (nt=8 is the ones-column -> row sums)
            #pragma unroll
            for (int ks = 0; ks < 4; ks++) {
                #pragma unroll
                for (int nt = 0; nt < 9; nt++) {
                    uint32_t b0, b1;
                    ldsm_x2t(b0, b1, smaddr(&Vsc[(ks * 16 + l15) * VST + nt * 8]));
                    MMA16(oacc[0][nt], sp[0][2*ks][0], sp[0][2*ks][1],
                          sp[0][2*ks+1][0], sp[0][2*ks+1][1], b0, b1);
                    MMA16(oacc[1][nt], sp[1][2*ks][0], sp[1][2*ks][1],
                          sp[1][2*ks+1][0], sp[1][2*ks+1][1], b0, b1);
                }
            }
        }
        if (jt + 1 <= jmax) CP_WAIT(0);
        __syncthreads();
    }

    // l lives in oacc[mt][8][0]/[2] of the tg==0 lane of each quad
    #pragma unroll
    for (int mt = 0; mt < 2; mt++) {
        const float l0 = __shfl_sync(0xffffffffu, oacc[mt][8][0], lane & 28);
        const float l1 = __shfl_sync(0xffffffffu, oacc[mt][8][2], lane & 28);
        const float inv0 = 1.0f / l0, inv1 = 1.0f / l1;
        const int r0 = roww + mt * 16 + g;
        const size_t ob0 = (size_t)(b * TT + r0) * DD + h * 64;
        const size_t ob1 = (size_t)(b * TT + r0 + 8) * DD + h * 64;
        #pragma unroll
        for (int nt = 0; nt < 8; nt++) {
            const int col = nt * 8 + 2 * tg;
            *reinterpret_cast<uint32_t*>(O + ob0 + col) =
                h2pack(oacc[mt][nt][0] * inv0, oacc[mt][nt][1] * inv0);
            *reinterpret_cast<uint32_t*>(O + ob1 + col) =
                h2pack(oacc[mt][nt][2] * inv1, oacc[mt][nt][3] * inv1);
        }
    }
}

// ===================== launch =====================
extern "C" void kernel_launch(void* const* d_in, const int* in_sizes, int n_in,
                              void* d_out, int out_size) {
    (void)in_sizes; (void)n_in; (void)out_size;
    const float* x   = (const float*)d_in[0];
    const float* g1  = (const float*)d_in[1];
    const float* bt1 = (const float*)d_in[2];
    const float* wq  = (const float*)d_in[3];
    const float* bq  = (const float*)d_in[4];
    const float* wk  = (const float*)d_in[5];
    const float* bk  = (const float*)d_in[6];
    const float* wv  = (const float*)d_in[7];
    const float* bv  = (const float*)d_in[8];
    const float* wo  = (const float*)d_in[9];
    const float* bo  = (const float*)d_in[10];
    const float* g2  = (const float*)d_in[11];
    const float* bt2 = (const float*)d_in[12];
    const float* w1  = (const float*)d_in[13];
    const float* b1  = (const float*)d_in[14];
    const float* w2  = (const float*)d_in[15];
    const float* b2  = (const float*)d_in[16];
    float* out = (float*)d_out;

    __half *h1, *q, *k, *v, *ao, *h2, *f1;
    float* x1;
    __half *hwq, *hwk, *hwv, *hwo, *hw1, *hw2;
    cudaGetSymbolAddress((void**)&h1, g_h1);
    cudaGetSymbolAddress((void**)&q,  g_q);
    cudaGetSymbolAddress((void**)&k,  g_k);
    cudaGetSymbolAddress((void**)&v,  g_v);
    cudaGetSymbolAddress((void**)&ao, g_ao);
    cudaGetSymbolAddress((void**)&x1, g_x1);
    cudaGetSymbolAddress((void**)&h2, g_h2);
    cudaGetSymbolAddress((void**)&f1, g_f1);
    cudaGetSymbolAddress((void**)&hwq, g_wq);
    cudaGetSymbolAddress((void**)&hwk, g_wk);
    cudaGetSymbolAddress((void**)&hwv, g_wv);
    cudaGetSymbolAddress((void**)&hwo, g_wo);
    cudaGetSymbolAddress((void**)&hw1, g_w1);
    cudaGetSymbolAddress((void**)&hw2, g_w2);

    const int ATTN_SMEM = ATTN_HALVES * (int)sizeof(__half);
    cudaFuncSetAttribute(attn_h, cudaFuncAttributeMaxDynamicSharedMemorySize, ATTN_SMEM);
    cudaFuncSetAttribute(gemm_h<1, true>,  cudaFuncAttributeMaxDynamicSharedMemorySize, GEMM_SMEM);
    cudaFuncSetAttribute(gemm_h<2, false>, cudaFuncAttributeMaxDynamicSharedMemorySize, GEMM_SMEM);
    cudaFuncSetAttribute(gemm_qkv,         cudaFuncAttributeMaxDynamicSharedMemorySize, GEMM_SMEM);

    // 0+1. fused: weights fp32->fp16 and h1 = LN(x)
    cvt_ln<<<CVT_BLOCKS + RR, 256>>>(wq, wk, wv, wo, w1, w2,
                                     hwq, hwk, hwv, hwo, hw1, hw2,
                                     x, g1, bt1, h1);
    // 2. fused q/k/v (q pre-scaled by 0.125*log2e)
    gemm_qkv<<<dim3(12, RR / 128), 256, GEMM_SMEM>>>(h1, hwq, bq, hwk, bk, hwv, bv, q, k, v);
    // 3. attention
    attn_h<<<dim3(TT / 128, 16, BB), 128, ATTN_SMEM>>>(q, k, v, ao);
    // 4. x1 = x + ao @ wo + bo   (fp32 out)
    gemm_h<2, false><<<dim3(DD / 128, RR / 128), 256, GEMM_SMEM>>>(ao, hwo, bo, x, x1, DD, DD);
    // 5. h2 = LN(x1)
    ln_kernel<<<RR, 256>>>(x1, g2, bt2, h2);
    // 6. f1 = gelu(h2 @ w1 + b1)  (fp16 out)
    gemm_h<1, true><<<dim3(4 * DD / 128, RR / 128), 256, GEMM_SMEM>>>(h2, hw1, b1, nullptr, f1, 4 * DD, DD);
    // 7. out = x1 + f1 @ w2 + b2  (fp32 out)
    gemm_h<2, false><<<dim3(DD / 128, RR / 128), 256, GEMM_SMEM>>>(f1, hw2, b2, x1, out, DD, 4 * DD);
}